// round 16
// baseline (speedup 1.0000x reference)
#include <cuda_runtime.h>
#include <cuda_bf16.h>
#include <math.h>

// ---------------- problem constants ----------------
#define STEPS 20000
#define NCOL  2048
#define CH    80            // steps per chunk
#define NCH   (STEPS/CH)    // 250 chunks
#define COLS  256           // columns per tile
#define CPB   (NCOL/COLS)   // 8 col-groups
#define TILES (NCH * CPB)   // 2000
#define NWORK (NCH * NCOL)
#define NBINS 200000
#define HISTN (NBINS + 1)
#define GRP   (CH/4)        // 20 four-step groups per chunk
#define DEP   5             // ucat ping-pong depth (groups); in-flight = DEP-1
#define NF1W  5             // ceil(CH/16) packed f1 words
#define SMEM_BYTES (CH*COLS*4 + DEP*4*COLS*4)   // 80 KB uexp + 20 KB ucat

#define R1_SUM_D 123020000.0
__device__ __constant__ float c_invr[4] = {
    1.0f / 1.0e6f, (float)(1.0 / R1_SUM_D), 1.0f / 1.0e5f, (float)(1.0 / 0.2)
};

__device__ __forceinline__ void get_thresholds(float& A, float& B, float& C) {
    const double c0 = 50000000.0 / R1_SUM_D;
    const double c2 = c0 + 3000000.0 / R1_SUM_D;
    const double c3 = c2 + 20000.0 / R1_SUM_D;
    A = (float)c0; B = (float)c2; C = (float)c3;
}

// ---- cp.async helpers ----
__device__ __forceinline__ void cpa4(unsigned smem, const void* g) {
    asm volatile("cp.async.ca.shared.global [%0], [%1], 4;" :: "r"(smem), "l"(g));
}
__device__ __forceinline__ void cpa_commit() {
    asm volatile("cp.async.commit_group;" ::: "memory");
}
template <int N>
__device__ __forceinline__ void cpa_wait() {
    asm volatile("cp.async.wait_group %0;" :: "n"(N) : "memory");
}

// ---- release/acquire flag ops ----
__device__ __forceinline__ unsigned ld_acq(const unsigned* p) {
    unsigned v;
    asm volatile("ld.acquire.gpu.global.b32 %0, [%1];" : "=r"(v) : "l"(p) : "memory");
    return v;
}
__device__ __forceinline__ void st_rel(unsigned* p, unsigned v) {
    asm volatile("st.release.gpu.global.b32 [%0], %1;" :: "l"(p), "r"(v) : "memory");
}

// ---------------- device scratch ----------------
__device__ unsigned char g_rentry[NWORK];   // entry state of chunk c, per col
__device__ double        g_roffs[NWORK];    // entry time offset of chunk c, per col
__device__ unsigned      g_flag[TILES];     // tile t published its successor's entry
__device__ unsigned      g_ticket;
__device__ int           g_hist[HISTN];

__device__ __forceinline__ int f1_of(float u, float A, float B, float C) {
    return (u < A) ? 0 : ((u < B) ? 2 : ((u < C) ? 3 : 0));
}
__device__ __forceinline__ int advance(int s, int f1) {
    return (s == 0) ? 1 : ((s == 1) ? f1 : 0);
}
__device__ __forceinline__ float invr_of(int s) {
    return (s == 0) ? c_invr[0] : ((s == 1) ? c_invr[1] : ((s == 2) ? c_invr[2] : c_invr[3]));
}

// smallest j in [0,NBINS] with (float)j*0.002f >= t (branchless +-2 correction)
__device__ __forceinline__ int bucket_arith(float t) {
    int j = (int)ceilf(t * 500.0f);
    j = max(0, min(j, NBINS));
    j += (j < NBINS) && ((float)j * 0.002f < t);
    j += (j < NBINS) && ((float)j * 0.002f < t);
    j -= (j > 0) && ((float)(j - 1) * 0.002f >= t);
    j -= (j > 0) && ((float)(j - 1) * 0.002f >= t);
    return j;
}

// ---------------- K0: reset hist + flags + ticket ----------------
__global__ void k_zero() {
    int i = blockIdx.x * blockDim.x + threadIdx.x;
    if (i < HISTN) g_hist[i] = 0;
    if (i < TILES) g_flag[i] = 0u;
    if (i == 0)    g_ticket = 0u;
}

// ---------------- fused: pass1 summaries + chained resolve + pass2 outputs ----------------
extern __shared__ float sh[];
__global__ void __launch_bounds__(COLS) k_fused(const float* __restrict__ ucat,
                                                const float* __restrict__ uexp,
                                                float* __restrict__ phot,
                                                float* __restrict__ cum) {
    __shared__ unsigned s_tile;
    int tid = threadIdx.x;
    if (tid == 0) s_tile = atomicAdd(&g_ticket, 1u);
    __syncthreads();
    unsigned tile = s_tile;
    int c  = (int)(tile >> 3);
    int cg = (int)(tile & 7u);
    int col = cg * COLS + tid;
    float A, B, C; get_thresholds(A, B, C);

    const float* pc = ucat + (size_t)c * CH * NCOL + col;
    const float* pe = uexp + (size_t)c * CH * NCOL + col;
    float* pp = phot + (size_t)c * CH * NCOL + col;
    float* pt = cum  + (size_t)c * CH * NCOL + col;

    float* sue = sh;                  // [k*COLS + tid], whole chunk
    unsigned ue_s = (unsigned)__cvta_generic_to_shared(sue) + tid * 4;
    unsigned uc_s = ue_s + CH * COLS * 4;           // ucat ping-pong base
    const unsigned ROW_B = COLS * 4;
    const unsigned STG_B = 4 * ROW_B;               // one 4-row group

    // prologue: DEP groups (4 ucat rows to slot, 4 uexp rows to final place)
    #pragma unroll
    for (int g = 0; g < DEP; g++) {
        #pragma unroll
        for (int j = 0; j < 4; j++) {
            cpa4(uc_s + g * STG_B + j * ROW_B, pc + (size_t)(4 * g + j) * NCOL);
            cpa4(ue_s + (unsigned)(4 * g + j) * ROW_B, pe + (size_t)(4 * g + j) * NCOL);
        }
        cpa_commit();
    }

    // ---- pass 1: summaries + packed f1 ----
    int   sA = 0, sB = 1, sC = 0;
    float aA = 0.f, aB = 0.f, aT = 0.f, g0 = 0.f;
    unsigned fw[NF1W];
    #pragma unroll
    for (int w = 0; w < NF1W; w++) fw[w] = 0u;

    for (int g = 0; g < GRP; g++) {
        if (g < GRP - DEP)       cpa_wait<DEP - 1>();
        else if (g == GRP - DEP) cpa_wait<0>();
        int buf = g % DEP;

        #pragma unroll
        for (int j = 0; j < 4; j++) {
            const int k = 4 * g + j;
            float u1 = sh[CH * COLS + (buf * 4 + j) * COLS + tid];
            float u2 = sue[k * COLS + tid];
            float gg = -__logf(1.0f - u2);
            int   f  = f1_of(u1, A, B, C);
            fw[k >> 4] |= (unsigned)f << (2 * (k & 15));
            if (k == 0) {
                g0 = gg;
                aA = gg * c_invr[0];
                aB = gg * c_invr[1];
                sA = 1; sB = f; sC = 0;
            } else {
                aT = fmaf(gg, invr_of(sC), aT);
                aA = fmaf(gg, invr_of(sA), aA);
                aB = fmaf(gg, invr_of(sB), aB);
                sC = advance(sC, f);
                sA = advance(sA, f);
                sB = advance(sB, f);
            }
        }
        if (g + DEP < GRP) {
            int nb = (g + DEP) % DEP;
            #pragma unroll
            for (int j = 0; j < 4; j++) {
                cpa4(uc_s + nb * STG_B + j * ROW_B, pc + (size_t)(4 * (g + DEP) + j) * NCOL);
                cpa4(ue_s + (unsigned)(4 * (g + DEP) + j) * ROW_B, pe + (size_t)(4 * (g + DEP) + j) * NCOL);
            }
            cpa_commit();
        }
    }
    float dA = aA, dB = aB;
    float dC = fmaf(g0, c_invr[2], aT);
    float dD = fmaf(g0, c_invr[3], aT);

    // ---- chained resolve ----
    int    entry = 0;
    double offs  = 0.0;
    if (c > 0) {
        if (tid == 0) {
            long long spins = 0;
            while (ld_acq(&g_flag[tile - 8]) == 0u) {
                __nanosleep(60);
                if (++spins > (1LL << 26)) break;   // safety valve: fail loud, not hang
            }
        }
        __syncthreads();
        entry = (int)g_rentry[(size_t)c * NCOL + col];
        offs  = g_roffs[(size_t)c * NCOL + col];
    }
    if (c + 1 < NCH) {
        int ex = (entry == 0) ? sA : ((entry == 1) ? sB : sC);
        float dv = (entry == 0) ? dA : (entry == 1) ? dB : (entry == 2) ? dC : dD;
        g_rentry[(size_t)(c + 1) * NCOL + col] = (unsigned char)ex;
        g_roffs[(size_t)(c + 1) * NCOL + col]  = offs + (double)dv;
        __syncthreads();
        if (tid == 0) st_rel(&g_flag[tile], 1u);
    }

    // ---- pass 2: outputs + histogram (uexp from smem, states via f1 regs) ----
    int   st = entry;
    float t  = (float)offs;
    int   jb = bucket_arith(t);
    float edge = (float)jb * 0.002f;
    int   rc = 0, nz = 0;
    const float IR0 = c_invr[0], IR1 = c_invr[1], IR2 = c_invr[2], IR3 = c_invr[3];

    for (int k = 0; k < CH; k++) {
        float u2 = sue[k * COLS + tid];
        float gg = -__logf(1.0f - u2);
        float ir = (st == 0) ? IR0 : ((st == 1) ? IR1 : ((st == 2) ? IR2 : IR3));
        t += gg * ir;
        bool ph = (st == 0);
        __stcs(pp + (size_t)k * NCOL, ph ? 1.0f : 0.0f);
        __stcs(pt + (size_t)k * NCOL, t);
        if (ph) {
            if (t > edge) {
                if (rc) atomicAdd(&g_hist[jb], rc);
                jb = bucket_arith(t); edge = (float)jb * 0.002f; rc = 1;
            } else rc++;
        } else nz++;
        int f = (int)((fw[k >> 4] >> (2 * (k & 15))) & 3u);
        st = advance(st, f);
    }
    if (rc) atomicAdd(&g_hist[jb], rc);

    int tot = __reduce_add_sync(0xffffffffu, nz);
    if ((tid & 31) == 0 && tot) atomicAdd(&g_hist[0], tot);
}

// ---------------- K4: int hist -> float32 output tail ----------------
__global__ void k_hist_out(float* __restrict__ out_hist) {
    int i = blockIdx.x * blockDim.x + threadIdx.x;
    if (i < HISTN) out_hist[i] = (float)g_hist[i];
}

// ---------------- launch ----------------
extern "C" void kernel_launch(void* const* d_in, const int* in_sizes, int n_in,
                              void* d_out, int out_size) {
    const float* ucat = (const float*)d_in[0];
    const float* uexp = (const float*)d_in[1];
    float* out = (float*)d_out;

    const size_t n_elem = (size_t)STEPS * NCOL;
    float* out_phot = out;
    float* out_cum  = out + n_elem;
    float* out_hist = out + 2 * n_elem;

    cudaFuncSetAttribute(k_fused, cudaFuncAttributeMaxDynamicSharedMemorySize, SMEM_BYTES);

    const int th = 256;
    const int zero_blocks = (HISTN + th - 1) / th;   // covers HISTN > TILES

    k_zero<<<zero_blocks, th>>>();
    k_fused<<<TILES, COLS, SMEM_BYTES>>>(ucat, uexp, out_phot, out_cum);
    k_hist_out<<<zero_blocks, th>>>(out_hist);
}